// round 2
// baseline (speedup 1.0000x reference)
#include <cuda_runtime.h>
#include <cstdint>

#define N_LEVELS 14
#define LOG2_T   19
#define T_MASK   ((1u << LOG2_T) - 1u)
#define TBL_SZ   (1u << LOG2_T)
#define WIDTH    64
#define D_IN     36
#define P1       2654435761u
#define P2       805459861u
#define NTHREADS 128

typedef unsigned long long ull;

__device__ __forceinline__ float tanh_fast(float x) {
    float y;
    asm("tanh.approx.f32 %0, %1;" : "=f"(y) : "f"(x));
    return y;
}
__device__ __forceinline__ ull pk(float lo, float hi) {
    ull r; asm("mov.b64 %0, {%1, %2};" : "=l"(r) : "f"(lo), "f"(hi)); return r;
}
__device__ __forceinline__ ull fma2(ull a, ull b, ull c) {
    ull d; asm("fma.rn.f32x2 %0, %1, %2, %3;" : "=l"(d) : "l"(a), "l"(b), "l"(c)); return d;
}
__device__ __forceinline__ float2 unpk(ull a) {
    float2 f; asm("mov.b64 {%0, %1}, %2;" : "=f"(f.x), "=f"(f.y) : "l"(a)); return f;
}

__global__ void __launch_bounds__(NTHREADS, 4)
deformnet_kernel(const float* __restrict__ x,
                 const float* __restrict__ e,
                 const float* __restrict__ tables,
                 const float* __restrict__ W1, const float* __restrict__ b1,
                 const float* __restrict__ W2, const float* __restrict__ b2,
                 const float* __restrict__ W3, const float* __restrict__ b3,
                 const float* __restrict__ bbox,
                 float* __restrict__ out, int n)
{
    // ---- transposed weights in shared: row j holds all inputs i (pairs are (i,i+1)) ----
    __shared__ __align__(16) float sW1t[WIDTH * D_IN];   // [64][36]  9216 B
    __shared__ __align__(16) float sW2t[WIDTH * WIDTH];  // [64][64] 16384 B
    __shared__ __align__(16) float sW3t[3 * WIDTH];      // [3][64]    768 B
    __shared__ float sB1[WIDTH], sB2[WIDTH], sB3[3];
    __shared__ float sBB[6];

    for (int t = threadIdx.x; t < D_IN * WIDTH; t += NTHREADS) {
        int i = t / WIDTH, j = t % WIDTH;           // coalesced global read
        sW1t[j * D_IN + i] = W1[t];
    }
    for (int t = threadIdx.x; t < WIDTH * WIDTH; t += NTHREADS) {
        int i = t / WIDTH, j = t % WIDTH;
        sW2t[j * WIDTH + i] = W2[t];
    }
    for (int t = threadIdx.x; t < WIDTH * 3; t += NTHREADS) {
        int i = t / 3, j = t % 3;
        sW3t[j * WIDTH + i] = W3[t];
    }
    if (threadIdx.x < WIDTH) { sB1[threadIdx.x] = b1[threadIdx.x]; sB2[threadIdx.x] = b2[threadIdx.x]; }
    if (threadIdx.x < 3) sB3[threadIdx.x] = b3[threadIdx.x];
    if (threadIdx.x < 6) sBB[threadIdx.x] = bbox[threadIdx.x];
    __syncthreads();

    int idx = blockIdx.x * NTHREADS + threadIdx.x;
    if (idx >= n) return;

    const float lo0 = sBB[0], lo1 = sBB[1], lo2 = sBB[2];
    const float hi0 = sBB[3], hi1 = sBB[4], hi2 = sBB[5];

    float xn0 = (x[idx * 3 + 0] - lo0) / (hi0 - lo0);
    float xn1 = (x[idx * 3 + 1] - lo1) / (hi1 - lo1);
    float xn2 = (x[idx * 3 + 2] - lo2) / (hi2 - lo2);

    // resolutions = floor(16 * 1.32^l)
    const float res_tab[N_LEVELS] = {16.f, 21.f, 27.f, 36.f, 48.f, 64.f, 84.f,
                                     111.f, 147.f, 194.f, 256.f, 339.f, 447.f, 590.f};

    ull inp[18];   // 18 packed input pairs (28 pe + 8 e)

    #pragma unroll
    for (int l = 0; l < N_LEVELS; l++) {
        const float r = res_tab[l];
        float px = xn0 * r, py = xn1 * r, pz = xn2 * r;
        float bx = floorf(px), by = floorf(py), bz = floorf(pz);
        float fx = px - bx, fy = py - by, fz = pz - bz;
        float wx = fx * fx * (3.f - 2.f * fx);
        float wy = fy * fy * (3.f - 2.f * fy);
        float wz = fz * fz * (3.f - 2.f * fz);

        unsigned ix = (unsigned)bx, iy = (unsigned)by, iz = (unsigned)bz;
        unsigned hx0 = ix,      hx1 = ix + 1u;
        unsigned hy0 = iy * P1, hy1 = (iy + 1u) * P1;
        unsigned hz0 = iz * P2, hz1 = (iz + 1u) * P2;

        const ull* __restrict__ tab = (const ull*)(tables) + (size_t)l * TBL_SZ;

        ull c000 = __ldg(&tab[(hx0 ^ hy0 ^ hz0) & T_MASK]);
        ull c001 = __ldg(&tab[(hx0 ^ hy0 ^ hz1) & T_MASK]);
        ull c010 = __ldg(&tab[(hx0 ^ hy1 ^ hz0) & T_MASK]);
        ull c011 = __ldg(&tab[(hx0 ^ hy1 ^ hz1) & T_MASK]);
        ull c100 = __ldg(&tab[(hx1 ^ hy0 ^ hz0) & T_MASK]);
        ull c101 = __ldg(&tab[(hx1 ^ hy0 ^ hz1) & T_MASK]);
        ull c110 = __ldg(&tab[(hx1 ^ hy1 ^ hz0) & T_MASK]);
        ull c111 = __ldg(&tab[(hx1 ^ hy1 ^ hz1) & T_MASK]);

        float ux = 1.f - wx, uy = 1.f - wy, uz = 1.f - wz;
        float w00 = ux * uy, w01 = ux * wy, w10 = wx * uy, w11 = wx * wy;
        float w000 = w00 * uz, w001 = w00 * wz;
        float w010 = w01 * uz, w011 = w01 * wz;
        float w100 = w10 * uz, w101 = w10 * wz;
        float w110 = w11 * uz, w111 = w11 * wz;

        // both features accumulated as one f32x2 pair
        ull acc = fma2(pk(w000, w000), c000, pk(0.f, 0.f));
        acc = fma2(pk(w001, w001), c001, acc);
        acc = fma2(pk(w010, w010), c010, acc);
        acc = fma2(pk(w011, w011), c011, acc);
        acc = fma2(pk(w100, w100), c100, acc);
        acc = fma2(pk(w101, w101), c101, acc);
        acc = fma2(pk(w110, w110), c110, acc);
        acc = fma2(pk(w111, w111), c111, acc);
        inp[l] = acc;
    }

    // extra features e [N,8] -> 4 pairs
    {
        const ulonglong2* e2 = (const ulonglong2*)(e + (size_t)idx * 8);
        ulonglong2 ea = __ldg(&e2[0]);
        ulonglong2 eb = __ldg(&e2[1]);
        inp[14] = ea.x; inp[15] = ea.y;
        inp[16] = eb.x; inp[17] = eb.y;
    }

    // ---- layer 1: [36] -> [64], tanh.  acc = {even-i partial, odd-i partial} ----
    ull h1p[32];
    float h_prev = 0.f;
    #pragma unroll
    for (int j = 0; j < WIDTH; j++) {
        ull acc = pk(sB1[j], 0.f);
        const ulonglong2* wrow = (const ulonglong2*)&sW1t[j * D_IN];
        #pragma unroll
        for (int q = 0; q < 9; q++) {
            ulonglong2 w = wrow[q];                  // 4 weights = 2 pairs
            acc = fma2(inp[2 * q + 0], w.x, acc);
            acc = fma2(inp[2 * q + 1], w.y, acc);
        }
        float2 s = unpk(acc);
        float h = tanh_fast(s.x + s.y);
        if (j & 1) h1p[j >> 1] = pk(h_prev, h); else h_prev = h;
    }

    // ---- layer 2: [64] -> [64], tanh ----
    ull h2p[32];
    #pragma unroll
    for (int j = 0; j < WIDTH; j++) {
        ull acc = pk(sB2[j], 0.f);
        const ulonglong2* wrow = (const ulonglong2*)&sW2t[j * WIDTH];
        #pragma unroll
        for (int q = 0; q < 16; q++) {
            ulonglong2 w = wrow[q];
            acc = fma2(h1p[2 * q + 0], w.x, acc);
            acc = fma2(h1p[2 * q + 1], w.y, acc);
        }
        float2 s = unpk(acc);
        float h = tanh_fast(s.x + s.y);
        if (j & 1) h2p[j >> 1] = pk(h_prev, h); else h_prev = h;
    }

    // ---- layer 3: [64] -> [3] ----
    float o[3];
    #pragma unroll
    for (int j = 0; j < 3; j++) {
        ull acc = pk(sB3[j], 0.f);
        const ulonglong2* wrow = (const ulonglong2*)&sW3t[j * WIDTH];
        #pragma unroll
        for (int q = 0; q < 16; q++) {
            ulonglong2 w = wrow[q];
            acc = fma2(h2p[2 * q + 0], w.x, acc);
            acc = fma2(h2p[2 * q + 1], w.y, acc);
        }
        float2 s = unpk(acc);
        o[j] = s.x + s.y;
    }

    // residual + rescale to bbox
    float o0 = (o[0] + xn0) * (hi0 - lo0) + lo0;
    float o1 = (o[1] + xn1) * (hi1 - lo1) + lo1;
    float o2 = (o[2] + xn2) * (hi2 - lo2) + lo2;

    out[idx * 3 + 0] = o0;
    out[idx * 3 + 1] = o1;
    out[idx * 3 + 2] = o2;
}

extern "C" void kernel_launch(void* const* d_in, const int* in_sizes, int n_in,
                              void* d_out, int out_size)
{
    const float* x      = (const float*)d_in[0];
    const float* e      = (const float*)d_in[1];
    const float* tables = (const float*)d_in[2];
    const float* W1     = (const float*)d_in[3];
    const float* b1     = (const float*)d_in[4];
    const float* W2     = (const float*)d_in[5];
    const float* b2     = (const float*)d_in[6];
    const float* W3     = (const float*)d_in[7];
    const float* b3     = (const float*)d_in[8];
    const float* bbox   = (const float*)d_in[9];
    float* out = (float*)d_out;

    int n = in_sizes[0] / 3;
    int grid = (n + NTHREADS - 1) / NTHREADS;
    deformnet_kernel<<<grid, NTHREADS>>>(x, e, tables, W1, b1, W2, b2, W3, b3, bbox, out, n);
}

// round 3
// speedup vs baseline: 1.3564x; 1.3564x over previous
#include <cuda_runtime.h>
#include <cuda_bf16.h>
#include <cstdint>

#define N_LEVELS 14
#define LOG2_T   19
#define T_MASK   ((1u << LOG2_T) - 1u)
#define TBL_SZ   (1u << LOG2_T)
#define WIDTH    64
#define P1       2654435761u
#define P2       805459861u
#define NTHREADS 128

typedef unsigned long long ull;

__device__ __forceinline__ float tanh_fast(float x) {
    float y;
    asm("tanh.approx.f32 %0, %1;" : "=f"(y) : "f"(x));
    return y;
}

union F4B2 { float4 f4; __nv_bfloat162 b2[4]; };

// W1 rows padded: 36 inputs -> 40 (20 bf16x2 pairs = 5 float4 per output row)
#define W1_STRIDE 40

__global__ void __launch_bounds__(NTHREADS, 4)
deformnet_kernel(const float* __restrict__ x,
                 const float* __restrict__ e,
                 const float* __restrict__ tables,
                 const float* __restrict__ W1, const float* __restrict__ b1,
                 const float* __restrict__ W2, const float* __restrict__ b2,
                 const float* __restrict__ W3, const float* __restrict__ b3,
                 const float* __restrict__ bbox,
                 float* __restrict__ out, int n)
{
    // Transposed bf16 weights in smem: row j holds inputs i, pairs (i, i+1).
    __shared__ __align__(16) __nv_bfloat16 sW1h[WIDTH * W1_STRIDE]; // 5120 B
    __shared__ __align__(16) __nv_bfloat16 sW2h[WIDTH * WIDTH];     // 8192 B
    __shared__ __align__(16) __nv_bfloat16 sW3h[3 * WIDTH];         //  384 B
    __shared__ float sB1[WIDTH], sB2[WIDTH], sB3[3];
    __shared__ float sBB[6];

    // single pass fill (no races: each smem slot written by exactly one thread)
    for (int t = threadIdx.x; t < WIDTH * W1_STRIDE; t += NTHREADS) {
        int j = t / W1_STRIDE, i = t % W1_STRIDE;
        float v = (i < 36) ? W1[i * WIDTH + j] : 0.f;
        sW1h[t] = __float2bfloat16(v);
    }
    for (int t = threadIdx.x; t < WIDTH * WIDTH; t += NTHREADS) {
        int i = t / WIDTH, j = t % WIDTH;
        sW2h[j * WIDTH + i] = __float2bfloat16(W2[t]);
    }
    for (int t = threadIdx.x; t < WIDTH * 3; t += NTHREADS) {
        int i = t / 3, j = t % 3;
        sW3h[j * WIDTH + i] = __float2bfloat16(W3[t]);
    }
    if (threadIdx.x < WIDTH) { sB1[threadIdx.x] = b1[threadIdx.x]; sB2[threadIdx.x] = b2[threadIdx.x]; }
    if (threadIdx.x < 3) sB3[threadIdx.x] = b3[threadIdx.x];
    if (threadIdx.x < 6) sBB[threadIdx.x] = bbox[threadIdx.x];
    __syncthreads();

    int idx = blockIdx.x * NTHREADS + threadIdx.x;
    if (idx >= n) return;

    const float lo0 = sBB[0], lo1 = sBB[1], lo2 = sBB[2];
    const float hi0 = sBB[3], hi1 = sBB[4], hi2 = sBB[5];

    float xn0 = (x[idx * 3 + 0] - lo0) / (hi0 - lo0);
    float xn1 = (x[idx * 3 + 1] - lo1) / (hi1 - lo1);
    float xn2 = (x[idx * 3 + 2] - lo2) / (hi2 - lo2);

    // resolutions = floor(16 * 1.32^l)
    const float res_tab[N_LEVELS] = {16.f, 21.f, 27.f, 36.f, 48.f, 64.f, 84.f,
                                     111.f, 147.f, 194.f, 256.f, 339.f, 447.f, 590.f};

    __nv_bfloat162 inp2[20];           // 14 pe pairs + 4 e pairs + 2 zero pads
    const ull* __restrict__ tabs = (const ull*)tables;

    // ---- encode: process levels in pairs, keep 16 gathers in flight ----
    #pragma unroll
    for (int lp = 0; lp < N_LEVELS / 2; lp++) {
        float wxs[2], wys[2], wzs[2];
        unsigned hidx[16];
        #pragma unroll
        for (int s = 0; s < 2; s++) {
            const int l = lp * 2 + s;
            const float r = res_tab[l];
            float px = xn0 * r, py = xn1 * r, pz = xn2 * r;
            float bx = floorf(px), by = floorf(py), bz = floorf(pz);
            float fx = px - bx, fy = py - by, fz = pz - bz;
            wxs[s] = fx * fx * (3.f - 2.f * fx);
            wys[s] = fy * fy * (3.f - 2.f * fy);
            wzs[s] = fz * fz * (3.f - 2.f * fz);

            unsigned ix = (unsigned)bx, iy = (unsigned)by, iz = (unsigned)bz;
            unsigned hx0 = ix,      hx1 = ix + 1u;
            unsigned hy0 = iy * P1, hy1 = (iy + 1u) * P1;
            unsigned hz0 = iz * P2, hz1 = (iz + 1u) * P2;
            const unsigned base = (unsigned)l << LOG2_T;

            hidx[s * 8 + 0] = base + ((hx0 ^ hy0 ^ hz0) & T_MASK);
            hidx[s * 8 + 1] = base + ((hx0 ^ hy0 ^ hz1) & T_MASK);
            hidx[s * 8 + 2] = base + ((hx0 ^ hy1 ^ hz0) & T_MASK);
            hidx[s * 8 + 3] = base + ((hx0 ^ hy1 ^ hz1) & T_MASK);
            hidx[s * 8 + 4] = base + ((hx1 ^ hy0 ^ hz0) & T_MASK);
            hidx[s * 8 + 5] = base + ((hx1 ^ hy0 ^ hz1) & T_MASK);
            hidx[s * 8 + 6] = base + ((hx1 ^ hy1 ^ hz0) & T_MASK);
            hidx[s * 8 + 7] = base + ((hx1 ^ hy1 ^ hz1) & T_MASK);
        }

        ull cc[16];
        #pragma unroll
        for (int q = 0; q < 16; q++) cc[q] = __ldg(&tabs[hidx[q]]);

        #pragma unroll
        for (int s = 0; s < 2; s++) {
            float wx = wxs[s], wy = wys[s], wz = wzs[s];
            float ux = 1.f - wx, uy = 1.f - wy, uz = 1.f - wz;
            float w00 = ux * uy, w01 = ux * wy, w10 = wx * uy, w11 = wx * wy;
            float cw[8] = { w00 * uz, w00 * wz, w01 * uz, w01 * wz,
                            w10 * uz, w10 * wz, w11 * uz, w11 * wz };
            float a0 = 0.f, a1 = 0.f;
            #pragma unroll
            for (int q = 0; q < 8; q++) {
                float2 c = *(float2*)&cc[s * 8 + q];
                a0 = fmaf(cw[q], c.x, a0);
                a1 = fmaf(cw[q], c.y, a1);
            }
            inp2[lp * 2 + s] = __floats2bfloat162_rn(a0, a1);
        }
    }

    // extra features e [N,8]
    {
        const float4* e4 = (const float4*)(e + (size_t)idx * 8);
        float4 ea = __ldg(&e4[0]);
        float4 eb = __ldg(&e4[1]);
        inp2[14] = __floats2bfloat162_rn(ea.x, ea.y);
        inp2[15] = __floats2bfloat162_rn(ea.z, ea.w);
        inp2[16] = __floats2bfloat162_rn(eb.x, eb.y);
        inp2[17] = __floats2bfloat162_rn(eb.z, eb.w);
    }
    inp2[18] = __floats2bfloat162_rn(0.f, 0.f);
    inp2[19] = inp2[18];

    const __nv_bfloat162 zero2 = __floats2bfloat162_rn(0.f, 0.f);

    // ---- layer 1: [36] -> [64], tanh ----
    __nv_bfloat162 h1p[32];
    float h_prev = 0.f;
    #pragma unroll
    for (int j = 0; j < WIDTH; j++) {
        const float4* row = (const float4*)&sW1h[j * W1_STRIDE];
        __nv_bfloat162 acc0 = zero2, acc1 = zero2;
        #pragma unroll
        for (int q = 0; q < 5; q++) {
            F4B2 u; u.f4 = row[q];
            acc0 = __hfma2(inp2[4 * q + 0], u.b2[0], acc0);
            acc1 = __hfma2(inp2[4 * q + 1], u.b2[1], acc1);
            acc0 = __hfma2(inp2[4 * q + 2], u.b2[2], acc0);
            acc1 = __hfma2(inp2[4 * q + 3], u.b2[3], acc1);
        }
        float2 s0 = __bfloat1622float2(acc0);
        float2 s1 = __bfloat1622float2(acc1);
        float h = tanh_fast(s0.x + s0.y + s1.x + s1.y + sB1[j]);
        if (j & 1) h1p[j >> 1] = __floats2bfloat162_rn(h_prev, h); else h_prev = h;
    }

    // ---- layer 2: [64] -> [64], tanh ----
    __nv_bfloat162 h2p[32];
    #pragma unroll
    for (int j = 0; j < WIDTH; j++) {
        const float4* row = (const float4*)&sW2h[j * WIDTH];
        __nv_bfloat162 acc0 = zero2, acc1 = zero2;
        #pragma unroll
        for (int q = 0; q < 8; q++) {
            F4B2 u; u.f4 = row[q];
            acc0 = __hfma2(h1p[4 * q + 0], u.b2[0], acc0);
            acc1 = __hfma2(h1p[4 * q + 1], u.b2[1], acc1);
            acc0 = __hfma2(h1p[4 * q + 2], u.b2[2], acc0);
            acc1 = __hfma2(h1p[4 * q + 3], u.b2[3], acc1);
        }
        float2 s0 = __bfloat1622float2(acc0);
        float2 s1 = __bfloat1622float2(acc1);
        float h = tanh_fast(s0.x + s0.y + s1.x + s1.y + sB2[j]);
        if (j & 1) h2p[j >> 1] = __floats2bfloat162_rn(h_prev, h); else h_prev = h;
    }

    // ---- layer 3: [64] -> [3] ----
    float o[3];
    #pragma unroll
    for (int j = 0; j < 3; j++) {
        const float4* row = (const float4*)&sW3h[j * WIDTH];
        __nv_bfloat162 acc0 = zero2, acc1 = zero2;
        #pragma unroll
        for (int q = 0; q < 8; q++) {
            F4B2 u; u.f4 = row[q];
            acc0 = __hfma2(h2p[4 * q + 0], u.b2[0], acc0);
            acc1 = __hfma2(h2p[4 * q + 1], u.b2[1], acc1);
            acc0 = __hfma2(h2p[4 * q + 2], u.b2[2], acc0);
            acc1 = __hfma2(h2p[4 * q + 3], u.b2[3], acc1);
        }
        float2 s0 = __bfloat1622float2(acc0);
        float2 s1 = __bfloat1622float2(acc1);
        o[j] = s0.x + s0.y + s1.x + s1.y + sB3[j];
    }

    // residual + rescale to bbox
    float o0 = (o[0] + xn0) * (hi0 - lo0) + lo0;
    float o1 = (o[1] + xn1) * (hi1 - lo1) + lo1;
    float o2 = (o[2] + xn2) * (hi2 - lo2) + lo2;

    out[idx * 3 + 0] = o0;
    out[idx * 3 + 1] = o1;
    out[idx * 3 + 2] = o2;
}

extern "C" void kernel_launch(void* const* d_in, const int* in_sizes, int n_in,
                              void* d_out, int out_size)
{
    const float* x      = (const float*)d_in[0];
    const float* e      = (const float*)d_in[1];
    const float* tables = (const float*)d_in[2];
    const float* W1     = (const float*)d_in[3];
    const float* b1     = (const float*)d_in[4];
    const float* W2     = (const float*)d_in[5];
    const float* b2     = (const float*)d_in[6];
    const float* W3     = (const float*)d_in[7];
    const float* b3     = (const float*)d_in[8];
    const float* bbox   = (const float*)d_in[9];
    float* out = (float*)d_out;

    int n = in_sizes[0] / 3;
    int grid = (n + NTHREADS - 1) / NTHREADS;
    deformnet_kernel<<<grid, NTHREADS>>>(x, e, tables, W1, b1, W2, b2, W3, b3, bbox, out, n);
}